// round 11
// baseline (speedup 1.0000x reference)
#include <cuda_runtime.h>
#include <cuda_bf16.h>
#include <cstdint>

#define B_SZ 8192
#define H_SZ 8
#define K_SZ 4096
#define HD   128
#define D_SZ 1024

// ---------------- static device scratch (no runtime allocation) ------------
__device__ float          g_zn  [(size_t)B_SZ * D_SZ];         // fp32 normalized z
__device__ float          g_cbn [(size_t)H_SZ * K_SZ * HD];    // fp32 normalized cb
__device__ __nv_bfloat16  g_zn16[(size_t)B_SZ * D_SZ];         // bf16
__device__ __nv_bfloat16  g_cbn16[(size_t)H_SZ * K_SZ * HD];   // bf16
__device__ unsigned g_tilemax[(size_t)B_SZ * H_SZ * 32];       // per-(row,128tile) fkey(max sim)

// ---------------- helpers ---------------------------------------------------
__device__ __forceinline__ uint32_t smem_u32(const void* p) {
    uint32_t a;
    asm("{ .reg .u64 t; cvta.to.shared.u64 t, %1; cvt.u32.u64 %0, t; }" : "=r"(a) : "l"(p));
    return a;
}
__device__ __forceinline__ void ldm4(uint32_t* r, uint32_t addr) {
    asm volatile("ldmatrix.sync.aligned.m8n8.x4.shared.b16 {%0,%1,%2,%3}, [%4];"
                 : "=r"(r[0]), "=r"(r[1]), "=r"(r[2]), "=r"(r[3]) : "r"(addr));
}
__device__ __forceinline__ void mma16816(float* c, const uint32_t* a,
                                         uint32_t b0, uint32_t b1) {
    asm volatile(
        "mma.sync.aligned.m16n8k16.row.col.f32.bf16.bf16.f32 "
        "{%0,%1,%2,%3},{%4,%5,%6,%7},{%8,%9},{%0,%1,%2,%3};"
        : "+f"(c[0]), "+f"(c[1]), "+f"(c[2]), "+f"(c[3])
        : "r"(a[0]), "r"(a[1]), "r"(a[2]), "r"(a[3]), "r"(b0), "r"(b1));
}
#define CP_ASYNC16(dst, src) \
    asm volatile("cp.async.cg.shared.global [%0], [%1], 16;" :: "r"(dst), "l"(src))
#define CP_COMMIT() asm volatile("cp.async.commit_group;" ::: "memory")
#define CP_WAIT0()  asm volatile("cp.async.wait_group 0;" ::: "memory")
#define CP_WAIT1()  asm volatile("cp.async.wait_group 1;" ::: "memory")

// order-preserving float<->uint key
__device__ __forceinline__ unsigned fkey(float f) {
    unsigned u = __float_as_uint(f);
    return (u & 0x80000000u) ? ~u : (u | 0x80000000u);
}
__device__ __forceinline__ float kinv(unsigned k) {
    return __uint_as_float((k & 0x80000000u) ? (k & 0x7fffffffu) : ~k);
}

// ---------------- fused normalization (z + codebooks, one launch) -----------
__global__ void norm_kernel(const float* __restrict__ z,
                            const float* __restrict__ cb) {
    int wid = threadIdx.x >> 5, lane = threadIdx.x & 31;
    size_t off;
    const float* srcp;
    float* dstf;
    __nv_bfloat16* dstb;
    if (blockIdx.x < B_SZ) {
        off  = (size_t)blockIdx.x * D_SZ + (size_t)wid * HD + (size_t)lane * 4;
        srcp = z;   dstf = g_zn;  dstb = g_zn16;
    } else {
        int r = (blockIdx.x - B_SZ) * 8 + wid;   // codebook row 0..H*K-1
        off  = (size_t)r * HD + (size_t)lane * 4;
        srcp = cb;  dstf = g_cbn; dstb = g_cbn16;
    }
    float4 a = *(const float4*)(srcp + off);
    float ss = a.x*a.x + a.y*a.y + a.z*a.z + a.w*a.w;
#pragma unroll
    for (int m = 16; m > 0; m >>= 1) ss += __shfl_xor_sync(0xffffffffu, ss, m);
    float d = fmaxf(sqrtf(ss), 1e-12f);
    float4 o = {a.x/d, a.y/d, a.z/d, a.w/d};
    *(float4*)(dstf + off) = o;
    uint2 p;
    p.x = ((unsigned)__bfloat16_as_ushort(__float2bfloat16_rn(o.y)) << 16) |
           (unsigned)__bfloat16_as_ushort(__float2bfloat16_rn(o.x));
    p.y = ((unsigned)__bfloat16_as_ushort(__float2bfloat16_rn(o.w)) << 16) |
           (unsigned)__bfloat16_as_ushort(__float2bfloat16_rn(o.z));
    *(uint2*)(dstb + off) = p;
}

// ---------------- HMMA GEMM: 64x64 CTAs, 4 CTAs/SM --------------------------
// CTA = 64 batch rows x (KT_PER_CTA x 64) codes, K=128. 4 warps in 2x2,
// warp tile 32x32. A in smem, B double-buffered cp.async. __stcs stores,
// per-(row,128-tile) max via fmaxf tree + global atomicMax(u32).
#define ROW_B   272
#define A_BYTES 17408          /* 64 rows * 272 B */
#define TILE_B  17408          /* 64 rows * 272 B */
#define SM_A    0
#define SM_B    17408
#define SM_TOT  52224
#define KT_PER_CTA 16          /* 16 tiles of 64 codes = 1024 codes per CTA */

__global__ void __launch_bounds__(128, 4) gemm_kernel(float* __restrict__ dist) {
    extern __shared__ char smem[];
    uint32_t sbase = smem_u32(smem);

    const int tid = threadIdx.x, wid = tid >> 5, lane = tid & 31;
    const int bt = blockIdx.x, h = blockIdx.y, kt0 = blockIdx.z * KT_PER_CTA;
    const int warp_m = wid >> 1, warp_n = wid & 1;

    // ---- issue A tile + first B tile ----
    const char* Ag = (const char*)(g_zn16 + (size_t)(bt * 64) * D_SZ + h * HD);
    const char* Bg = (const char*)(g_cbn16 +
                     ((size_t)h * K_SZ + (size_t)kt0 * 64) * HD);
#pragma unroll
    for (int it = 0; it < 8; it++) {
        int idx = it * 128 + tid;
        int row = idx >> 4, c = idx & 15;
        CP_ASYNC16(sbase + SM_A + row * ROW_B + c * 16,
                   Ag + (size_t)row * (D_SZ * 2) + c * 16);
    }
#pragma unroll
    for (int it = 0; it < 8; it++) {
        int idx = it * 128 + tid;
        int row = idx >> 4, c = idx & 15;
        CP_ASYNC16(sbase + SM_B + row * ROW_B + c * 16,
                   Bg + (size_t)row * 256 + c * 16);
    }
    CP_COMMIT();

    // ldmatrix lane bases (validated fragment mapping)
    const uint32_t a_base = sbase + SM_A +
        (uint32_t)((warp_m * 32 + ((lane >> 3) & 1) * 8 + (lane & 7)) * ROW_B +
                   (lane >> 4) * 16);
    const uint32_t b_off =
        (uint32_t)((warp_n * 32 + (lane >> 4) * 8 + (lane & 7)) * ROW_B +
                   ((lane >> 3) & 1) * 16);

    for (int kti = 0; kti < KT_PER_CTA; kti++) {
        const int kt = kt0 + kti;   // global 64-code tile index (0..63)
        if (kti < KT_PER_CTA - 1) {
            const char* Bn = Bg + (size_t)(kti + 1) * 64 * 256;
            uint32_t bdst = sbase + SM_B + ((kti + 1) & 1) * TILE_B;
#pragma unroll
            for (int it = 0; it < 8; it++) {
                int idx = it * 128 + tid;
                int row = idx >> 4, c = idx & 15;
                CP_ASYNC16(bdst + row * ROW_B + c * 16,
                           Bn + (size_t)row * 256 + c * 16);
            }
            CP_COMMIT();
            CP_WAIT1();
        } else {
            CP_WAIT0();
        }
        __syncthreads();

        const uint32_t b_base = sbase + SM_B + (kti & 1) * TILE_B + b_off;

        float acc[2][4][4];
#pragma unroll
        for (int mt = 0; mt < 2; mt++)
#pragma unroll
            for (int j = 0; j < 4; j++)
#pragma unroll
                for (int r = 0; r < 4; r++) acc[mt][j][r] = 0.0f;

#pragma unroll
        for (int ks = 0; ks < 8; ks++) {
            uint32_t af[2][4], bf[2][4];
            ldm4(af[0], a_base + ks * 32);
            ldm4(af[1], a_base + 16 * ROW_B + ks * 32);
            ldm4(bf[0], b_base + ks * 32);
            ldm4(bf[1], b_base + 16 * ROW_B + ks * 32);
#pragma unroll
            for (int mt = 0; mt < 2; mt++)
#pragma unroll
                for (int j = 0; j < 4; j++)
                    mma16816(acc[mt][j], af[mt],
                             bf[j >> 1][(j & 1) ? 2 : 0],
                             bf[j >> 1][(j & 1) ? 3 : 1]);
        }
        // all warps done reading this B buffer before next prefetch overwrites
        __syncthreads();

        // ---- epilogue: streaming stores + per-(row,128tile) max ----
#pragma unroll
        for (int mt = 0; mt < 2; mt++) {
            int r0  = warp_m * 32 + mt * 16 + (lane >> 2);
            int gb0 = bt * 64 + r0;
            int kc  = kt * 64 + warp_n * 32 + (lane & 3) * 2;
            float* p0 = dist + ((size_t)gb0 * H_SZ + h) * K_SZ + kc;
            float* p1 = p0 + (size_t)8 * H_SZ * K_SZ;
            float best0 = -2.0f, best1 = -2.0f;
#pragma unroll
            for (int j = 0; j < 4; j++) {
                float c0 = acc[mt][j][0], c1 = acc[mt][j][1];
                float c2 = acc[mt][j][2], c3 = acc[mt][j][3];
                __stcs((float2*)(p0 + j * 8), make_float2(1.0f - c0, 1.0f - c1));
                __stcs((float2*)(p1 + j * 8), make_float2(1.0f - c2, 1.0f - c3));
                best0 = fmaxf(best0, fmaxf(c0, c1));
                best1 = fmaxf(best1, fmaxf(c2, c3));
            }
#pragma unroll
            for (int m = 1; m <= 2; m <<= 1) {
                best0 = fmaxf(best0, __shfl_xor_sync(0xffffffffu, best0, m));
                best1 = fmaxf(best1, __shfl_xor_sync(0xffffffffu, best1, m));
            }
            if ((lane & 3) == 0) {
                atomicMax(&g_tilemax[((size_t)gb0 * H_SZ + h) * 32 + (kt >> 1)],
                          fkey(best0));
                atomicMax(&g_tilemax[((size_t)(gb0 + 8) * H_SZ + h) * 32 + (kt >> 1)],
                          fkey(best1));
            }
        }
    }
}

// ---------------- rescue: tile-max guided exact argmax ----------------------
#define MARGIN 8e-3f
__global__ void __launch_bounds__(256) rescue_kernel(const float* __restrict__ dist,
                                                     const float* __restrict__ cb,
                                                     float* __restrict__ zq,
                                                     float* __restrict__ idx_out) {
    int w = blockIdx.x * 8 + (threadIdx.x >> 5);  // (b*H + h)
    int lane = threadIdx.x & 31;
    int b = w >> 3, h = w & 7;

    unsigned tkey = g_tilemax[(size_t)w * 32 + lane];
    unsigned gbest = tkey;
#pragma unroll
    for (int m = 16; m > 0; m >>= 1)
        gbest = max(gbest, __shfl_xor_sync(0xffffffffu, gbest, m));
    float thr = kinv(gbest) - MARGIN;

    float4 zv = ((const float4*)(g_zn + (size_t)b * D_SZ + (size_t)h * HD))[lane];

    unsigned long long best = 0ull;
    unsigned tmask = __ballot_sync(0xffffffffu, kinv(tkey) >= thr);
    while (tmask) {
        int t = __ffs(tmask) - 1;
        tmask &= tmask - 1;
        float4 dv = ((const float4*)(dist + (size_t)w * K_SZ + t * 128))[lane];
        float s4[4] = {1.0f - dv.x, 1.0f - dv.y, 1.0f - dv.z, 1.0f - dv.w};
#pragma unroll
        for (int j = 0; j < 4; j++) {
            unsigned pm = __ballot_sync(0xffffffffu, s4[j] >= thr);
            while (pm) {
                int src = __ffs(pm) - 1;
                pm &= pm - 1;
                int k = t * 128 + src * 4 + j;
                float4 cv = ((const float4*)(g_cbn +
                             ((size_t)h * K_SZ + k) * HD))[lane];
                float p = fmaf(zv.x, cv.x,
                          fmaf(zv.y, cv.y, fmaf(zv.z, cv.z, zv.w * cv.w)));
#pragma unroll
                for (int m = 16; m > 0; m >>= 1)
                    p += __shfl_xor_sync(0xffffffffu, p, m);
                unsigned long long key =
                    ((unsigned long long)fkey(p) << 32) | (unsigned)(K_SZ - 1 - k);
                if (key > best) best = key;
            }
        }
    }
    int kbest = (K_SZ - 1) - (int)(best & 0xffffffffull);
    if (lane == 0) idx_out[w] = (float)kbest;
    float4 c = *(const float4*)(cb + ((size_t)h * K_SZ + kbest) * HD +
                                (size_t)lane * 4);
    *(float4*)(zq + (size_t)b * D_SZ + (size_t)h * HD + (size_t)lane * 4) = c;
}

// ---------------------------------------------------------------------------
extern "C" void kernel_launch(void* const* d_in, const int* in_sizes, int n_in,
                              void* d_out, int out_size) {
    const float* z  = (const float*)d_in[0];
    const float* cb = (const float*)d_in[1];
    float* out = (float*)d_out;

    float* zq   = out;
    float* idxo = out + (size_t)B_SZ * D_SZ;
    float* dist = out + (size_t)B_SZ * D_SZ + (size_t)B_SZ * H_SZ;

    cudaFuncSetAttribute(gemm_kernel,
                         cudaFuncAttributeMaxDynamicSharedMemorySize, SM_TOT);

    norm_kernel<<<B_SZ + H_SZ * K_SZ / 8, 256>>>(z, cb);

    dim3 grid(B_SZ / 64, H_SZ, 64 / KT_PER_CTA);
    gemm_kernel<<<grid, 128, SM_TOT>>>(dist);

    rescue_kernel<<<B_SZ * H_SZ / 8, 256>>>(dist, cb, zq, idxo);
}

// round 12
// speedup vs baseline: 1.0423x; 1.0423x over previous
#include <cuda_runtime.h>
#include <cuda_bf16.h>
#include <cstdint>

#define B_SZ 8192
#define H_SZ 8
#define K_SZ 4096
#define HD   128
#define D_SZ 1024

// ---------------- static device scratch (no runtime allocation) ------------
__device__ __nv_bfloat16  g_zn16[(size_t)B_SZ * D_SZ];         // bf16 normalized z
__device__ __nv_bfloat16  g_cbn16[(size_t)H_SZ * K_SZ * HD];   // bf16 normalized cb
__device__ unsigned g_tilemax[(size_t)B_SZ * H_SZ * 32];       // per-(row,128tile) fkey(max sim)

// ---------------- helpers ---------------------------------------------------
__device__ __forceinline__ uint32_t smem_u32(const void* p) {
    uint32_t a;
    asm("{ .reg .u64 t; cvta.to.shared.u64 t, %1; cvt.u32.u64 %0, t; }" : "=r"(a) : "l"(p));
    return a;
}
__device__ __forceinline__ void ldm4(uint32_t* r, uint32_t addr) {
    asm volatile("ldmatrix.sync.aligned.m8n8.x4.shared.b16 {%0,%1,%2,%3}, [%4];"
                 : "=r"(r[0]), "=r"(r[1]), "=r"(r[2]), "=r"(r[3]) : "r"(addr));
}
__device__ __forceinline__ void mma16816(float* c, const uint32_t* a,
                                         uint32_t b0, uint32_t b1) {
    asm volatile(
        "mma.sync.aligned.m16n8k16.row.col.f32.bf16.bf16.f32 "
        "{%0,%1,%2,%3},{%4,%5,%6,%7},{%8,%9},{%0,%1,%2,%3};"
        : "+f"(c[0]), "+f"(c[1]), "+f"(c[2]), "+f"(c[3])
        : "r"(a[0]), "r"(a[1]), "r"(a[2]), "r"(a[3]), "r"(b0), "r"(b1));
}
#define CP_ASYNC16(dst, src) \
    asm volatile("cp.async.cg.shared.global [%0], [%1], 16;" :: "r"(dst), "l"(src))
#define CP_COMMIT() asm volatile("cp.async.commit_group;" ::: "memory")
#define CP_WAIT0()  asm volatile("cp.async.wait_group 0;" ::: "memory")
#define CP_WAIT1()  asm volatile("cp.async.wait_group 1;" ::: "memory")

// order-preserving float<->uint key
__device__ __forceinline__ unsigned fkey(float f) {
    unsigned u = __float_as_uint(f);
    return (u & 0x80000000u) ? ~u : (u | 0x80000000u);
}
__device__ __forceinline__ float kinv(unsigned k) {
    return __uint_as_float((k & 0x80000000u) ? (k & 0x7fffffffu) : ~k);
}

// ---------------- fused normalization (bf16 outputs only) -------------------
__global__ void norm_kernel(const float* __restrict__ z,
                            const float* __restrict__ cb) {
    int wid = threadIdx.x >> 5, lane = threadIdx.x & 31;
    size_t off;
    const float* srcp;
    __nv_bfloat16* dstb;
    if (blockIdx.x < B_SZ) {
        off  = (size_t)blockIdx.x * D_SZ + (size_t)wid * HD + (size_t)lane * 4;
        srcp = z;   dstb = g_zn16;
    } else {
        int r = (blockIdx.x - B_SZ) * 8 + wid;   // codebook row 0..H*K-1
        off  = (size_t)r * HD + (size_t)lane * 4;
        srcp = cb;  dstb = g_cbn16;
    }
    float4 a = *(const float4*)(srcp + off);
    float ss = a.x*a.x + a.y*a.y + a.z*a.z + a.w*a.w;
#pragma unroll
    for (int m = 16; m > 0; m >>= 1) ss += __shfl_xor_sync(0xffffffffu, ss, m);
    float d = fmaxf(sqrtf(ss), 1e-12f);
    float4 o = {a.x/d, a.y/d, a.z/d, a.w/d};
    uint2 p;
    p.x = ((unsigned)__bfloat16_as_ushort(__float2bfloat16_rn(o.y)) << 16) |
           (unsigned)__bfloat16_as_ushort(__float2bfloat16_rn(o.x));
    p.y = ((unsigned)__bfloat16_as_ushort(__float2bfloat16_rn(o.w)) << 16) |
           (unsigned)__bfloat16_as_ushort(__float2bfloat16_rn(o.z));
    *(uint2*)(dstb + off) = p;
}

// ---------------- HMMA GEMM (R10 config: 128x128, persistent, 2 CTAs/SM) ----
#define ROW_B   272
#define TILE_B  34816          /* 128 rows * 272 B */
#define SM_A    0
#define SM_B    34816
#define SM_TOT  104448
#define KT_PER_CTA 8

__global__ void __launch_bounds__(256, 2) gemm_kernel(float* __restrict__ dist) {
    extern __shared__ char smem[];
    uint32_t sbase = smem_u32(smem);

    const int tid = threadIdx.x, wid = tid >> 5, lane = tid & 31;
    const int bt = blockIdx.x, h = blockIdx.y, kt0 = blockIdx.z * KT_PER_CTA;
    const int warp_m = wid >> 2, warp_n = wid & 3;

    // ---- issue A tile + first B tile ----
    const char* Ag = (const char*)(g_zn16 + (size_t)(bt * 128) * D_SZ + h * HD);
    const char* Bg = (const char*)(g_cbn16 +
                     ((size_t)h * K_SZ + (size_t)kt0 * 128) * HD);
#pragma unroll
    for (int it = 0; it < 8; it++) {
        int idx = it * 256 + tid;
        int row = idx >> 4, c = idx & 15;
        CP_ASYNC16(sbase + SM_A + row * ROW_B + c * 16,
                   Ag + (size_t)row * (D_SZ * 2) + c * 16);
    }
#pragma unroll
    for (int it = 0; it < 8; it++) {
        int idx = it * 256 + tid;
        int row = idx >> 4, c = idx & 15;
        CP_ASYNC16(sbase + SM_B + row * ROW_B + c * 16,
                   Bg + (size_t)row * 256 + c * 16);
    }
    CP_COMMIT();

    // ldmatrix lane bases (validated mapping)
    const uint32_t a_base = sbase + SM_A +
        (uint32_t)((warp_m * 64 + ((lane >> 3) & 1) * 8 + (lane & 7)) * ROW_B +
                   (lane >> 4) * 16);
    const uint32_t b_off =
        (uint32_t)((warp_n * 32 + (lane >> 4) * 8 + (lane & 7)) * ROW_B +
                   ((lane >> 3) & 1) * 16);

    for (int kti = 0; kti < KT_PER_CTA; kti++) {
        const int kt = kt0 + kti;
        if (kti < KT_PER_CTA - 1) {
            const char* Bn = Bg + (size_t)(kti + 1) * 128 * 256;
            uint32_t bdst = sbase + SM_B + ((kti + 1) & 1) * TILE_B;
#pragma unroll
            for (int it = 0; it < 8; it++) {
                int idx = it * 256 + tid;
                int row = idx >> 4, c = idx & 15;
                CP_ASYNC16(bdst + row * ROW_B + c * 16,
                           Bn + (size_t)row * 256 + c * 16);
            }
            CP_COMMIT();
            CP_WAIT1();
        } else {
            CP_WAIT0();
        }
        __syncthreads();

        const uint32_t b_base = sbase + SM_B + (kti & 1) * TILE_B + b_off;

        float acc[4][4][4];
#pragma unroll
        for (int mt = 0; mt < 4; mt++)
#pragma unroll
            for (int j = 0; j < 4; j++)
#pragma unroll
                for (int r = 0; r < 4; r++) acc[mt][j][r] = 0.0f;

#pragma unroll
        for (int ks = 0; ks < 8; ks++) {
            uint32_t af[4][4], bf[2][4];
#pragma unroll
            for (int mt = 0; mt < 4; mt++)
                ldm4(af[mt], a_base + mt * (16 * ROW_B) + ks * 32);
            ldm4(bf[0], b_base + ks * 32);
            ldm4(bf[1], b_base + 16 * ROW_B + ks * 32);
#pragma unroll
            for (int mt = 0; mt < 4; mt++)
#pragma unroll
                for (int j = 0; j < 4; j++)
                    mma16816(acc[mt][j], af[mt],
                             bf[j >> 1][(j & 1) ? 2 : 0],
                             bf[j >> 1][(j & 1) ? 3 : 1]);
        }
        // all warps done reading this B buffer before next prefetch overwrites
        __syncthreads();

        // ---- epilogue: streaming stores + per-(row,tile) max (fmaxf tree) ----
#pragma unroll
        for (int mt = 0; mt < 4; mt++) {
            int r0  = warp_m * 64 + mt * 16 + (lane >> 2);
            int gb0 = bt * 128 + r0;
            int kc  = kt * 128 + warp_n * 32 + (lane & 3) * 2;
            float* p0 = dist + ((size_t)gb0 * H_SZ + h) * K_SZ + kc;
            float* p1 = p0 + (size_t)8 * H_SZ * K_SZ;
            float best0 = -2.0f, best1 = -2.0f;
#pragma unroll
            for (int j = 0; j < 4; j++) {
                float c0 = acc[mt][j][0], c1 = acc[mt][j][1];
                float c2 = acc[mt][j][2], c3 = acc[mt][j][3];
                __stcs((float2*)(p0 + j * 8), make_float2(1.0f - c0, 1.0f - c1));
                __stcs((float2*)(p1 + j * 8), make_float2(1.0f - c2, 1.0f - c3));
                best0 = fmaxf(best0, fmaxf(c0, c1));
                best1 = fmaxf(best1, fmaxf(c2, c3));
            }
#pragma unroll
            for (int m = 1; m <= 2; m <<= 1) {
                best0 = fmaxf(best0, __shfl_xor_sync(0xffffffffu, best0, m));
                best1 = fmaxf(best1, __shfl_xor_sync(0xffffffffu, best1, m));
            }
            if ((lane & 3) == 0) {
                atomicMax(&g_tilemax[((size_t)gb0 * H_SZ + h) * 32 + kt],
                          fkey(best0));
                atomicMax(&g_tilemax[((size_t)(gb0 + 8) * H_SZ + h) * 32 + kt],
                          fkey(best1));
            }
        }
    }
}

// ---------------- rescue: tile-max guided exact argmax ----------------------
// On-the-fly renormalization of z and cb rows: elementwise identical fp32
// values to a precomputed normalize (same ops), so argmax is unchanged.
#define MARGIN 8e-3f
__global__ void __launch_bounds__(256) rescue_kernel(const float* __restrict__ dist,
                                                     const float* __restrict__ z,
                                                     const float* __restrict__ cb,
                                                     float* __restrict__ zq,
                                                     float* __restrict__ idx_out) {
    int w = blockIdx.x * 8 + (threadIdx.x >> 5);  // (b*H + h)
    int lane = threadIdx.x & 31;
    int b = w >> 3, h = w & 7;

    unsigned tkey = g_tilemax[(size_t)w * 32 + lane];
    unsigned gbest = tkey;
#pragma unroll
    for (int m = 16; m > 0; m >>= 1)
        gbest = max(gbest, __shfl_xor_sync(0xffffffffu, gbest, m));
    float thr = kinv(gbest) - MARGIN;

    // normalized z slice for this lane (bitwise == norm_kernel's fp32 output)
    float4 zv;
    {
        float4 a = ((const float4*)(z + (size_t)b * D_SZ + (size_t)h * HD))[lane];
        float ss = a.x*a.x + a.y*a.y + a.z*a.z + a.w*a.w;
#pragma unroll
        for (int m = 16; m > 0; m >>= 1) ss += __shfl_xor_sync(0xffffffffu, ss, m);
        float d = fmaxf(sqrtf(ss), 1e-12f);
        zv.x = a.x/d; zv.y = a.y/d; zv.z = a.z/d; zv.w = a.w/d;
    }

    unsigned long long best = 0ull;
    unsigned tmask = __ballot_sync(0xffffffffu, kinv(tkey) >= thr);
    while (tmask) {
        int t = __ffs(tmask) - 1;
        tmask &= tmask - 1;
        float4 dv = ((const float4*)(dist + (size_t)w * K_SZ + t * 128))[lane];
        float s4[4] = {1.0f - dv.x, 1.0f - dv.y, 1.0f - dv.z, 1.0f - dv.w};
#pragma unroll
        for (int j = 0; j < 4; j++) {
            unsigned pm = __ballot_sync(0xffffffffu, s4[j] >= thr);
            while (pm) {
                int src = __ffs(pm) - 1;
                pm &= pm - 1;
                int k = t * 128 + src * 4 + j;
                float4 cr = ((const float4*)(cb +
                             ((size_t)h * K_SZ + k) * HD))[lane];
                float cs = cr.x*cr.x + cr.y*cr.y + cr.z*cr.z + cr.w*cr.w;
#pragma unroll
                for (int m = 16; m > 0; m >>= 1)
                    cs += __shfl_xor_sync(0xffffffffu, cs, m);
                float cd = fmaxf(sqrtf(cs), 1e-12f);
                float4 cv = {cr.x/cd, cr.y/cd, cr.z/cd, cr.w/cd};
                float p = fmaf(zv.x, cv.x,
                          fmaf(zv.y, cv.y, fmaf(zv.z, cv.z, zv.w * cv.w)));
#pragma unroll
                for (int m = 16; m > 0; m >>= 1)
                    p += __shfl_xor_sync(0xffffffffu, p, m);
                unsigned long long key =
                    ((unsigned long long)fkey(p) << 32) | (unsigned)(K_SZ - 1 - k);
                if (key > best) best = key;
            }
        }
    }
    int kbest = (K_SZ - 1) - (int)(best & 0xffffffffull);
    if (lane == 0) idx_out[w] = (float)kbest;
    float4 c = *(const float4*)(cb + ((size_t)h * K_SZ + kbest) * HD +
                                (size_t)lane * 4);
    *(float4*)(zq + (size_t)b * D_SZ + (size_t)h * HD + (size_t)lane * 4) = c;
}

// ---------------------------------------------------------------------------
extern "C" void kernel_launch(void* const* d_in, const int* in_sizes, int n_in,
                              void* d_out, int out_size) {
    const float* z  = (const float*)d_in[0];
    const float* cb = (const float*)d_in[1];
    float* out = (float*)d_out;

    float* zq   = out;
    float* idxo = out + (size_t)B_SZ * D_SZ;
    float* dist = out + (size_t)B_SZ * D_SZ + (size_t)B_SZ * H_SZ;

    cudaFuncSetAttribute(gemm_kernel,
                         cudaFuncAttributeMaxDynamicSharedMemorySize, SM_TOT);

    norm_kernel<<<B_SZ + H_SZ * K_SZ / 8, 256>>>(z, cb);

    dim3 grid(B_SZ / 128, H_SZ, 32 / KT_PER_CTA);
    gemm_kernel<<<grid, 256, SM_TOT>>>(dist);

    rescue_kernel<<<B_SZ * H_SZ / 8, 256>>>(dist, z, cb, zq, idxo);
}

// round 15
// speedup vs baseline: 1.0652x; 1.0219x over previous
#include <cuda_runtime.h>
#include <cuda_bf16.h>
#include <cstdint>

#define B_SZ 8192
#define H_SZ 8
#define K_SZ 4096
#define HD   128
#define D_SZ 1024

// ---------------- static device scratch (no runtime allocation) ------------
__device__ float          g_zn  [(size_t)B_SZ * D_SZ];         // fp32 normalized z
__device__ float          g_cbn [(size_t)H_SZ * K_SZ * HD];    // fp32 normalized cb
__device__ __nv_bfloat16  g_zn16[(size_t)B_SZ * D_SZ];         // bf16
__device__ __nv_bfloat16  g_cbn16[(size_t)H_SZ * K_SZ * HD];   // bf16
__device__ unsigned g_tilemax[(size_t)B_SZ * H_SZ * 32];       // per-(row,128tile) fkey(max sim)

// ---------------- helpers ---------------------------------------------------
__device__ __forceinline__ uint32_t smem_u32(const void* p) {
    uint32_t a;
    asm("{ .reg .u64 t; cvta.to.shared.u64 t, %1; cvt.u32.u64 %0, t; }" : "=r"(a) : "l"(p));
    return a;
}
__device__ __forceinline__ void ldm4(uint32_t* r, uint32_t addr) {
    asm volatile("ldmatrix.sync.aligned.m8n8.x4.shared.b16 {%0,%1,%2,%3}, [%4];"
                 : "=r"(r[0]), "=r"(r[1]), "=r"(r[2]), "=r"(r[3]) : "r"(addr));
}
__device__ __forceinline__ void mma16816(float* c, const uint32_t* a,
                                         uint32_t b0, uint32_t b1) {
    asm volatile(
        "mma.sync.aligned.m16n8k16.row.col.f32.bf16.bf16.f32 "
        "{%0,%1,%2,%3},{%4,%5,%6,%7},{%8,%9},{%0,%1,%2,%3};"
        : "+f"(c[0]), "+f"(c[1]), "+f"(c[2]), "+f"(c[3])
        : "r"(a[0]), "r"(a[1]), "r"(a[2]), "r"(a[3]), "r"(b0), "r"(b1));
}
#define CP_ASYNC16(dst, src) \
    asm volatile("cp.async.cg.shared.global [%0], [%1], 16;" :: "r"(dst), "l"(src))
#define CP_COMMIT() asm volatile("cp.async.commit_group;" ::: "memory")
#define CP_WAIT0()  asm volatile("cp.async.wait_group 0;" ::: "memory")
#define CP_WAIT1()  asm volatile("cp.async.wait_group 1;" ::: "memory")

// order-preserving float<->uint key
__device__ __forceinline__ unsigned fkey(float f) {
    unsigned u = __float_as_uint(f);
    return (u & 0x80000000u) ? ~u : (u | 0x80000000u);
}
__device__ __forceinline__ float kinv(unsigned k) {
    return __uint_as_float((k & 0x80000000u) ? (k & 0x7fffffffu) : ~k);
}

// ---------------- fused normalization (z + codebooks, one launch) -----------
__global__ void norm_kernel(const float* __restrict__ z,
                            const float* __restrict__ cb) {
    int wid = threadIdx.x >> 5, lane = threadIdx.x & 31;
    size_t off;
    const float* srcp;
    float* dstf;
    __nv_bfloat16* dstb;
    if (blockIdx.x < B_SZ) {
        off  = (size_t)blockIdx.x * D_SZ + (size_t)wid * HD + (size_t)lane * 4;
        srcp = z;   dstf = g_zn;  dstb = g_zn16;
    } else {
        int r = (blockIdx.x - B_SZ) * 8 + wid;   // codebook row 0..H*K-1
        off  = (size_t)r * HD + (size_t)lane * 4;
        srcp = cb;  dstf = g_cbn; dstb = g_cbn16;
    }
    float4 a = *(const float4*)(srcp + off);
    float ss = a.x*a.x + a.y*a.y + a.z*a.z + a.w*a.w;
#pragma unroll
    for (int m = 16; m > 0; m >>= 1) ss += __shfl_xor_sync(0xffffffffu, ss, m);
    float d = fmaxf(sqrtf(ss), 1e-12f);
    float4 o = {a.x/d, a.y/d, a.z/d, a.w/d};
    *(float4*)(dstf + off) = o;
    uint2 p;
    p.x = ((unsigned)__bfloat16_as_ushort(__float2bfloat16_rn(o.y)) << 16) |
           (unsigned)__bfloat16_as_ushort(__float2bfloat16_rn(o.x));
    p.y = ((unsigned)__bfloat16_as_ushort(__float2bfloat16_rn(o.w)) << 16) |
           (unsigned)__bfloat16_as_ushort(__float2bfloat16_rn(o.z));
    *(uint2*)(dstb + off) = p;
}

// ---------------- HMMA GEMM (128x128, persistent, 2 CTAs/SM) ----------------
#define ROW_B   272
#define TILE_B  34816          /* 128 rows * 272 B */
#define SM_A    0
#define SM_B    34816
#define SM_TOT  104448
#define KT_PER_CTA 4           /* 4 tiles of 128 codes -> 4096 CTAs, 13.8 waves */

__global__ void __launch_bounds__(256, 2) gemm_kernel(float* __restrict__ dist) {
    extern __shared__ char smem[];
    uint32_t sbase = smem_u32(smem);

    const int tid = threadIdx.x, wid = tid >> 5, lane = tid & 31;
    const int bt = blockIdx.x, h = blockIdx.y, kt0 = blockIdx.z * KT_PER_CTA;
    const int warp_m = wid >> 2, warp_n = wid & 3;

    // ---- issue A tile + first B tile ----
    const char* Ag = (const char*)(g_zn16 + (size_t)(bt * 128) * D_SZ + h * HD);
    const char* Bg = (const char*)(g_cbn16 +
                     ((size_t)h * K_SZ + (size_t)kt0 * 128) * HD);
#pragma unroll
    for (int it = 0; it < 8; it++) {
        int idx = it * 256 + tid;
        int row = idx >> 4, c = idx & 15;
        CP_ASYNC16(sbase + SM_A + row * ROW_B + c * 16,
                   Ag + (size_t)row * (D_SZ * 2) + c * 16);
    }
#pragma unroll
    for (int it = 0; it < 8; it++) {
        int idx = it * 256 + tid;
        int row = idx >> 4, c = idx & 15;
        CP_ASYNC16(sbase + SM_B + row * ROW_B + c * 16,
                   Bg + (size_t)row * 256 + c * 16);
    }
    CP_COMMIT();

    // ldmatrix lane bases (validated mapping)
    const uint32_t a_base = sbase + SM_A +
        (uint32_t)((warp_m * 64 + ((lane >> 3) & 1) * 8 + (lane & 7)) * ROW_B +
                   (lane >> 4) * 16);
    const uint32_t b_off =
        (uint32_t)((warp_n * 32 + (lane >> 4) * 8 + (lane & 7)) * ROW_B +
                   ((lane >> 3) & 1) * 16);

    for (int kti = 0; kti < KT_PER_CTA; kti++) {
        const int kt = kt0 + kti;
        if (kti < KT_PER_CTA - 1) {
            const char* Bn = Bg + (size_t)(kti + 1) * 128 * 256;
            uint32_t bdst = sbase + SM_B + ((kti + 1) & 1) * TILE_B;
#pragma unroll
            for (int it = 0; it < 8; it++) {
                int idx = it * 256 + tid;
                int row = idx >> 4, c = idx & 15;
                CP_ASYNC16(bdst + row * ROW_B + c * 16,
                           Bn + (size_t)row * 256 + c * 16);
            }
            CP_COMMIT();
            CP_WAIT1();
        } else {
            CP_WAIT0();
        }
        __syncthreads();

        const uint32_t b_base = sbase + SM_B + (kti & 1) * TILE_B + b_off;

        float acc[4][4][4];
#pragma unroll
        for (int mt = 0; mt < 4; mt++)
#pragma unroll
            for (int j = 0; j < 4; j++)
#pragma unroll
                for (int r = 0; r < 4; r++) acc[mt][j][r] = 0.0f;

#pragma unroll
        for (int ks = 0; ks < 8; ks++) {
            uint32_t af[4][4], bf[2][4];
#pragma unroll
            for (int mt = 0; mt < 4; mt++)
                ldm4(af[mt], a_base + mt * (16 * ROW_B) + ks * 32);
            ldm4(bf[0], b_base + ks * 32);
            ldm4(bf[1], b_base + 16 * ROW_B + ks * 32);
#pragma unroll
            for (int mt = 0; mt < 4; mt++)
#pragma unroll
                for (int j = 0; j < 4; j++)
                    mma16816(acc[mt][j], af[mt],
                             bf[j >> 1][(j & 1) ? 2 : 0],
                             bf[j >> 1][(j & 1) ? 3 : 1]);
        }
        // all warps done reading this B buffer before next prefetch overwrites
        __syncthreads();

        // ---- epilogue: streaming stores + per-(row,tile) max (fmaxf tree) ----
#pragma unroll
        for (int mt = 0; mt < 4; mt++) {
            int r0  = warp_m * 64 + mt * 16 + (lane >> 2);
            int gb0 = bt * 128 + r0;
            int kc  = kt * 128 + warp_n * 32 + (lane & 3) * 2;
            float* p0 = dist + ((size_t)gb0 * H_SZ + h) * K_SZ + kc;
            float* p1 = p0 + (size_t)8 * H_SZ * K_SZ;
            float best0 = -2.0f, best1 = -2.0f;
#pragma unroll
            for (int j = 0; j < 4; j++) {
                float c0 = acc[mt][j][0], c1 = acc[mt][j][1];
                float c2 = acc[mt][j][2], c3 = acc[mt][j][3];
                __stcs((float2*)(p0 + j * 8), make_float2(1.0f - c0, 1.0f - c1));
                __stcs((float2*)(p1 + j * 8), make_float2(1.0f - c2, 1.0f - c3));
                best0 = fmaxf(best0, fmaxf(c0, c1));
                best1 = fmaxf(best1, fmaxf(c2, c3));
            }
#pragma unroll
            for (int m = 1; m <= 2; m <<= 1) {
                best0 = fmaxf(best0, __shfl_xor_sync(0xffffffffu, best0, m));
                best1 = fmaxf(best1, __shfl_xor_sync(0xffffffffu, best1, m));
            }
            if ((lane & 3) == 0) {
                atomicMax(&g_tilemax[((size_t)gb0 * H_SZ + h) * 32 + kt],
                          fkey(best0));
                atomicMax(&g_tilemax[((size_t)(gb0 + 8) * H_SZ + h) * 32 + kt],
                          fkey(best1));
            }
        }
    }
}

// ---------------- rescue: tile-max guided exact argmax ----------------------
#define MARGIN 8e-3f
__global__ void __launch_bounds__(256) rescue_kernel(const float* __restrict__ dist,
                                                     const float* __restrict__ cb,
                                                     float* __restrict__ zq,
                                                     float* __restrict__ idx_out) {
    int w = blockIdx.x * 8 + (threadIdx.x >> 5);  // (b*H + h)
    int lane = threadIdx.x & 31;
    int b = w >> 3, h = w & 7;

    unsigned tkey = g_tilemax[(size_t)w * 32 + lane];
    unsigned gbest = tkey;
#pragma unroll
    for (int m = 16; m > 0; m >>= 1)
        gbest = max(gbest, __shfl_xor_sync(0xffffffffu, gbest, m));
    float thr = kinv(gbest) - MARGIN;

    float4 zv = ((const float4*)(g_zn + (size_t)b * D_SZ + (size_t)h * HD))[lane];

    unsigned long long best = 0ull;
    unsigned tmask = __ballot_sync(0xffffffffu, kinv(tkey) >= thr);
    while (tmask) {
        int t = __ffs(tmask) - 1;
        tmask &= tmask - 1;
        float4 dv = ((const float4*)(dist + (size_t)w * K_SZ + t * 128))[lane];
        float s4[4] = {1.0f - dv.x, 1.0f - dv.y, 1.0f - dv.z, 1.0f - dv.w};
#pragma unroll
        for (int j = 0; j < 4; j++) {
            unsigned pm = __ballot_sync(0xffffffffu, s4[j] >= thr);
            while (pm) {
                int src = __ffs(pm) - 1;
                pm &= pm - 1;
                int k = t * 128 + src * 4 + j;
                float4 cv = ((const float4*)(g_cbn +
                             ((size_t)h * K_SZ + k) * HD))[lane];
                float p = fmaf(zv.x, cv.x,
                          fmaf(zv.y, cv.y, fmaf(zv.z, cv.z, zv.w * cv.w)));
#pragma unroll
                for (int m = 16; m > 0; m >>= 1)
                    p += __shfl_xor_sync(0xffffffffu, p, m);
                unsigned long long key =
                    ((unsigned long long)fkey(p) << 32) | (unsigned)(K_SZ - 1 - k);
                if (key > best) best = key;
            }
        }
    }
    int kbest = (K_SZ - 1) - (int)(best & 0xffffffffull);
    if (lane == 0) idx_out[w] = (float)kbest;
    float4 c = *(const float4*)(cb + ((size_t)h * K_SZ + kbest) * HD +
                                (size_t)lane * 4);
    *(float4*)(zq + (size_t)b * D_SZ + (size_t)h * HD + (size_t)lane * 4) = c;
}

// ---------------------------------------------------------------------------
extern "C" void kernel_launch(void* const* d_in, const int* in_sizes, int n_in,
                              void* d_out, int out_size) {
    const float* z  = (const float*)d_in[0];
    const float* cb = (const float*)d_in[1];
    float* out = (float*)d_out;

    float* zq   = out;
    float* idxo = out + (size_t)B_SZ * D_SZ;
    float* dist = out + (size_t)B_SZ * D_SZ + (size_t)B_SZ * H_SZ;

    cudaFuncSetAttribute(gemm_kernel,
                         cudaFuncAttributeMaxDynamicSharedMemorySize, SM_TOT);

    norm_kernel<<<B_SZ + H_SZ * K_SZ / 8, 256>>>(z, cb);

    dim3 grid(B_SZ / 128, H_SZ, 32 / KT_PER_CTA);
    gemm_kernel<<<grid, 256, SM_TOT>>>(dist);

    rescue_kernel<<<B_SZ * H_SZ / 8, 256>>>(dist, cb, zq, idxo);
}